// round 2
// baseline (speedup 1.0000x reference)
#include <cuda_runtime.h>
#include <cstdint>
#include <cstddef>

#define T_TOK 8192
#define D_IN  4096
#define D_OUT 4096
#define RANK  16
#define NA    8

#define BM 128
#define BN 128
#define BK 32
#define STAGES 4
#define SMEM_STRIDE 36            // floats per smem row (32 data + 4 pad; keeps 16B align, kills bank conflicts)
#define STAGE_FLOATS (128 * SMEM_STRIDE)
#define KTILES (D_IN / BK)        // 128

// Scratch (allocation-free rule: __device__ globals)
__device__ float g_Hs[T_TOK * RANK];   // h_t scaled by scaling[a_t]
__device__ int   g_adp[T_TOK];         // adapter id per token

// ---------------------------------------------------------------------------
// helpers
// ---------------------------------------------------------------------------
__device__ __forceinline__ int seg_of(const int* __restrict__ seg, int t) {
    // searchsorted(seg, t, 'right') - 1, clipped to [0, NA-1]
    int s = 0;
#pragma unroll
    for (int i = 1; i <= NA; i++) s += (seg[i] <= t) ? 1 : 0;
    return s < (NA - 1) ? s : (NA - 1);
}

__device__ __forceinline__ uint32_t smem_u32(const void* p) {
    return (uint32_t)__cvta_generic_to_shared(p);
}

__device__ __forceinline__ void cp16(uint32_t dst, const void* src) {
    asm volatile("cp.async.cg.shared.global [%0], [%1], 16;\n" ::"r"(dst), "l"(src));
}
#define CP_COMMIT() asm volatile("cp.async.commit_group;\n")
#define CP_WAIT2()  asm volatile("cp.async.wait_group 2;\n")

__device__ __forceinline__ uint32_t f2tf(float f) {
    uint32_t u;
    asm("cvt.rna.tf32.f32 %0, %1;" : "=r"(u) : "f"(f));
    return u;
}

__device__ __forceinline__ void mma_tf32(float* c, const uint32_t* a, const uint32_t* b) {
    asm volatile(
        "mma.sync.aligned.m16n8k8.row.col.f32.tf32.tf32.f32 "
        "{%0,%1,%2,%3},{%4,%5,%6,%7},{%8,%9},{%0,%1,%2,%3};\n"
        : "+f"(c[0]), "+f"(c[1]), "+f"(c[2]), "+f"(c[3])
        : "r"(a[0]), "r"(a[1]), "r"(a[2]), "r"(a[3]), "r"(b[0]), "r"(b[1]));
}

// ---------------------------------------------------------------------------
// Kernel 1: H[t, r] = scaling[a_t] * sum_k x[t,k] * wa[a_t, k, r]; also g_adp[t]
// Block: 64 tokens, 256 threads = (16 token groups of 4) x (16 r)
// ---------------------------------------------------------------------------
__global__ __launch_bounds__(256) void lora_h_kernel(
    const float* __restrict__ x, const float* __restrict__ wa,
    const float* __restrict__ scaling, const int* __restrict__ segment,
    const int* __restrict__ lora_ids)
{
    __shared__ float xs[64][68];
    const int tid = threadIdx.x;
    const int tg  = tid >> 4;     // 0..15
    const int r   = tid & 15;     // 0..15
    const int t0  = blockIdx.x * 64;
    const int tr0 = tg * 4;

    int a[4];
#pragma unroll
    for (int i = 0; i < 4; i++) a[i] = lora_ids[seg_of(segment, t0 + tr0 + i)];
    const bool uni = (a[0] == a[1]) && (a[1] == a[2]) && (a[2] == a[3]);

    float acc[4] = {0.f, 0.f, 0.f, 0.f};

    for (int kc = 0; kc < D_IN; kc += 64) {
        __syncthreads();
#pragma unroll
        for (int j = 0; j < 4; j++) {
            int idx = tid + j * 256;          // 0..1023
            int row = idx >> 4;               // 64 rows
            int c4  = idx & 15;               // 16 float4 per row
            float4 v = *reinterpret_cast<const float4*>(
                x + (size_t)(t0 + row) * D_IN + kc + c4 * 4);
            *reinterpret_cast<float4*>(&xs[row][c4 * 4]) = v;
        }
        __syncthreads();

        if (uni) {
            const float* wp = wa + (size_t)a[0] * D_IN * RANK + (size_t)kc * RANK + r;
#pragma unroll 8
            for (int k = 0; k < 64; k++) {
                float w = __ldg(wp + k * RANK);
                acc[0] += xs[tr0 + 0][k] * w;
                acc[1] += xs[tr0 + 1][k] * w;
                acc[2] += xs[tr0 + 2][k] * w;
                acc[3] += xs[tr0 + 3][k] * w;
            }
        } else {
#pragma unroll 4
            for (int k = 0; k < 64; k++) {
#pragma unroll
                for (int i = 0; i < 4; i++) {
                    float w = __ldg(wa + (size_t)a[i] * D_IN * RANK +
                                    (size_t)(kc + k) * RANK + r);
                    acc[i] += xs[tr0 + i][k] * w;
                }
            }
        }
    }

#pragma unroll
    for (int i = 0; i < 4; i++) {
        int t = t0 + tr0 + i;
        g_Hs[t * RANK + r] = acc[i] * scaling[a[i]];
        if (r == 0) g_adp[t] = a[i];
    }
}

// ---------------------------------------------------------------------------
// Kernel 2: fused base GEMM (tf32 mma.sync) + bias + LoRA epilogue
// out[t, o] = sum_k x[t,k] * W[o,k] + b[o] + sum_j Hs[t,j] * wb[a_t, j, o]
// 128x128 tile, BK=32, 4-stage cp.async, 8 warps (2 m x 4 n), warp tile 64x32
// ---------------------------------------------------------------------------
__global__ __launch_bounds__(256, 1) void fused_gemm_kernel(
    const float* __restrict__ x, const float* __restrict__ w,
    const float* __restrict__ bias, const float* __restrict__ wb,
    float* __restrict__ out)
{
    extern __shared__ float smem[];
    float* As = smem;                            // [STAGES][128][36]
    float* Bs = smem + STAGES * STAGE_FLOATS;    // [STAGES][128][36]

    const int tid  = threadIdx.x;
    const int bn   = blockIdx.x;   // n tile (x-fastest: W row-wave stays L2-resident)
    const int bm   = blockIdx.y;   // m tile
    const int lane = tid & 31;
    const int warp = tid >> 5;
    const int wm   = warp & 1;     // 0..1
    const int wn   = warp >> 1;    // 0..3
    const int g    = lane >> 2;    // 0..7
    const int t4   = lane & 3;     // 0..3

    const float* gA = x + (size_t)(bm * BM) * D_IN;  // rows of x
    const float* gB = w + (size_t)(bn * BN) * D_IN;  // rows of W (=[N][K])

    float c[4][4][4];
#pragma unroll
    for (int mi = 0; mi < 4; mi++)
#pragma unroll
        for (int ni = 0; ni < 4; ni++)
#pragma unroll
            for (int q = 0; q < 4; q++) c[mi][ni][q] = 0.f;

    // prologue: stages 0..STAGES-2
#pragma unroll
    for (int s = 0; s < STAGES - 1; s++) {
        float* sA = As + s * STAGE_FLOATS;
        float* sB = Bs + s * STAGE_FLOATS;
        int k0 = s * BK;
#pragma unroll
        for (int i = 0; i < 4; i++) {
            int idx = tid + i * 256;
            int row = idx >> 3;
            int c4  = idx & 7;
            cp16(smem_u32(sA + row * SMEM_STRIDE + c4 * 4),
                 gA + (size_t)row * D_IN + k0 + c4 * 4);
            cp16(smem_u32(sB + row * SMEM_STRIDE + c4 * 4),
                 gB + (size_t)row * D_IN + k0 + c4 * 4);
        }
        CP_COMMIT();
    }

    for (int kt = 0; kt < KTILES; kt++) {
        CP_WAIT2();
        __syncthreads();

        // issue stage kt+STAGES-1
        if (kt + STAGES - 1 < KTILES) {
            int s = (kt + STAGES - 1) & (STAGES - 1);
            float* sA = As + s * STAGE_FLOATS;
            float* sB = Bs + s * STAGE_FLOATS;
            int k0 = (kt + STAGES - 1) * BK;
#pragma unroll
            for (int i = 0; i < 4; i++) {
                int idx = tid + i * 256;
                int row = idx >> 3;
                int c4  = idx & 7;
                cp16(smem_u32(sA + row * SMEM_STRIDE + c4 * 4),
                     gA + (size_t)row * D_IN + k0 + c4 * 4);
                cp16(smem_u32(sB + row * SMEM_STRIDE + c4 * 4),
                     gB + (size_t)row * D_IN + k0 + c4 * 4);
            }
        }
        CP_COMMIT();

        const float* sA = As + (kt & (STAGES - 1)) * STAGE_FLOATS;
        const float* sB = Bs + (kt & (STAGES - 1)) * STAGE_FLOATS;

#pragma unroll
        for (int kk = 0; kk < 4; kk++) {
            const int k0 = kk * 8;
            uint32_t af[4][4], bf[4][2];
#pragma unroll
            for (int mi = 0; mi < 4; mi++) {
                int rr = wm * 64 + mi * 16 + g;
                af[mi][0] = f2tf(sA[rr * SMEM_STRIDE + k0 + t4]);
                af[mi][1] = f2tf(sA[(rr + 8) * SMEM_STRIDE + k0 + t4]);
                af[mi][2] = f2tf(sA[rr * SMEM_STRIDE + k0 + t4 + 4]);
                af[mi][3] = f2tf(sA[(rr + 8) * SMEM_STRIDE + k0 + t4 + 4]);
            }
#pragma unroll
            for (int ni = 0; ni < 4; ni++) {
                int cc = wn * 32 + ni * 8 + g;
                bf[ni][0] = f2tf(sB[cc * SMEM_STRIDE + k0 + t4]);
                bf[ni][1] = f2tf(sB[cc * SMEM_STRIDE + k0 + t4 + 4]);
            }
#pragma unroll
            for (int mi = 0; mi < 4; mi++)
#pragma unroll
                for (int ni = 0; ni < 4; ni++)
                    mma_tf32(c[mi][ni], af[mi], bf[ni]);
        }
    }

    // ---------------- epilogue: bias + LoRA + store ----------------
    const int rbase = bm * BM + wm * 64;
    const int cbase = bn * BN + wn * 32;

    int trow[8], ta[8];
#pragma unroll
    for (int mi = 0; mi < 4; mi++)
#pragma unroll
        for (int hh = 0; hh < 2; hh++) {
            int t = rbase + mi * 16 + g + 8 * hh;
            trow[mi * 2 + hh] = t;
            ta[mi * 2 + hh] = g_adp[t];
        }
    bool uni = true;
#pragma unroll
    for (int q = 1; q < 8; q++) uni = uni && (ta[q] == ta[0]);

    if (uni) {
        const float* wbp = wb + (size_t)ta[0] * RANK * D_OUT;
#pragma unroll
        for (int ni = 0; ni < 4; ni++) {
            const int o = cbase + ni * 8 + t4 * 2;
            const float2 bv = *reinterpret_cast<const float2*>(bias + o);
            float2 wv[16];
#pragma unroll
            for (int j = 0; j < 16; j++)
                wv[j] = *reinterpret_cast<const float2*>(wbp + j * D_OUT + o);
#pragma unroll
            for (int mi = 0; mi < 4; mi++)
#pragma unroll
                for (int hh = 0; hh < 2; hh++) {
                    const int t = trow[mi * 2 + hh];
                    const float4* hp = reinterpret_cast<const float4*>(g_Hs + t * RANK);
                    float hreg[16];
                    *reinterpret_cast<float4*>(&hreg[0])  = hp[0];
                    *reinterpret_cast<float4*>(&hreg[4])  = hp[1];
                    *reinterpret_cast<float4*>(&hreg[8])  = hp[2];
                    *reinterpret_cast<float4*>(&hreg[12]) = hp[3];
                    float l0 = 0.f, l1 = 0.f;
#pragma unroll
                    for (int j = 0; j < 16; j++) {
                        l0 = fmaf(hreg[j], wv[j].x, l0);
                        l1 = fmaf(hreg[j], wv[j].y, l1);
                    }
                    float2 res;
                    res.x = c[mi][ni][2 * hh + 0] + bv.x + l0;
                    res.y = c[mi][ni][2 * hh + 1] + bv.y + l1;
                    *reinterpret_cast<float2*>(out + (size_t)t * D_OUT + o) = res;
                }
        }
    } else {
        // rare: thread's rows span a segment boundary
#pragma unroll
        for (int q = 0; q < 8; q++) {
            const int mi = q >> 1, hh = q & 1;
            const int t = trow[q];
            const float* wbp = wb + (size_t)ta[q] * RANK * D_OUT;
            const float4* hp = reinterpret_cast<const float4*>(g_Hs + t * RANK);
            float hreg[16];
            *reinterpret_cast<float4*>(&hreg[0])  = hp[0];
            *reinterpret_cast<float4*>(&hreg[4])  = hp[1];
            *reinterpret_cast<float4*>(&hreg[8])  = hp[2];
            *reinterpret_cast<float4*>(&hreg[12]) = hp[3];
#pragma unroll
            for (int ni = 0; ni < 4; ni++) {
                const int o = cbase + ni * 8 + t4 * 2;
                float l0 = bias[o], l1 = bias[o + 1];
#pragma unroll
                for (int j = 0; j < 16; j++) {
                    l0 = fmaf(hreg[j], __ldg(wbp + j * D_OUT + o), l0);
                    l1 = fmaf(hreg[j], __ldg(wbp + j * D_OUT + o + 1), l1);
                }
                float2 res;
                res.x = c[mi][ni][2 * hh + 0] + l0;
                res.y = c[mi][ni][2 * hh + 1] + l1;
                *reinterpret_cast<float2*>(out + (size_t)t * D_OUT + o) = res;
            }
        }
    }
}

// ---------------------------------------------------------------------------
extern "C" void kernel_launch(void* const* d_in, const int* in_sizes, int n_in,
                              void* d_out, int out_size)
{
    (void)in_sizes; (void)n_in; (void)out_size;
    const float* x       = (const float*)d_in[0];
    const float* base_w  = (const float*)d_in[1];
    const float* base_b  = (const float*)d_in[2];
    const float* wa      = (const float*)d_in[3];
    const float* wb      = (const float*)d_in[4];
    const float* scaling = (const float*)d_in[5];
    const int*   segment = (const int*)d_in[6];
    const int*   lora_id = (const int*)d_in[7];
    float* out = (float*)d_out;

    lora_h_kernel<<<T_TOK / 64, 256>>>(x, wa, scaling, segment, lora_id);

    const int smem_bytes = STAGES * 2 * STAGE_FLOATS * (int)sizeof(float);  // 147456
    cudaFuncSetAttribute(fused_gemm_kernel,
                         cudaFuncAttributeMaxDynamicSharedMemorySize, smem_bytes);
    dim3 grid(D_OUT / BN, T_TOK / BM);  // (32, 64)
    fused_gemm_kernel<<<grid, 256, smem_bytes>>>(x, base_w, base_b, wb, out);
}

// round 4
// speedup vs baseline: 1.2172x; 1.2172x over previous
#include <cuda_runtime.h>
#include <cstdint>
#include <cstddef>

#define T_TOK 8192
#define D_IN  4096
#define D_OUT 4096
#define RANK  16
#define NA    8

// ---- GEMM tile config ----
#define BM 128
#define BN 128
#define BK 32
#define STAGES 3
#define KTILES (D_IN / BK)          // 128
#define A_STAGE_B 16384             // 128 rows x 32 k x 4B
#define B_STAGE_B 16384
#define SMEM_TOTAL (STAGES * (A_STAGE_B + B_STAGE_B))   // 98304

// ---- scratch (__device__ globals; no allocation allowed) ----
// x permuted to mma A-fragment order: [m16][k8][lane][4], RNE-rounded to tf32
__device__ float g_xa[(size_t)T_TOK * D_IN];
// W permuted to mma B-fragment order: [n8][k16][lane][4], RNE-rounded to tf32
__device__ float g_wb2[(size_t)D_OUT * D_IN];
__device__ float g_Hs[T_TOK * RANK];
__device__ int   g_adp[T_TOK];

// ===========================================================================
// helpers
// ===========================================================================
__device__ __forceinline__ uint32_t smem_u32(const void* p) {
    return (uint32_t)__cvta_generic_to_shared(p);
}
__device__ __forceinline__ uint32_t f2tf(float f) {
    uint32_t u;
    asm("cvt.rna.tf32.f32 %0, %1;" : "=r"(u) : "f"(f));
    return u;
}
__device__ __forceinline__ void cp16(uint32_t dst, const void* src) {
    asm volatile("cp.async.cg.shared.global [%0], [%1], 16;\n" ::"r"(dst), "l"(src));
}
#define CP_COMMIT() asm volatile("cp.async.commit_group;\n")
#define CP_WAIT1()  asm volatile("cp.async.wait_group 1;\n")

__device__ __forceinline__ uint4 lds128(uint32_t a) {
    uint4 v;
    asm volatile("ld.shared.v4.b32 {%0,%1,%2,%3}, [%4];"
                 : "=r"(v.x), "=r"(v.y), "=r"(v.z), "=r"(v.w) : "r"(a));
    return v;
}
__device__ __forceinline__ void mma_tf32(float* c, const uint4& a, uint32_t b0, uint32_t b1) {
    asm volatile(
        "mma.sync.aligned.m16n8k8.row.col.f32.tf32.tf32.f32 "
        "{%0,%1,%2,%3},{%4,%5,%6,%7},{%8,%9},{%0,%1,%2,%3};\n"
        : "+f"(c[0]), "+f"(c[1]), "+f"(c[2]), "+f"(c[3])
        : "r"(a.x), "r"(a.y), "r"(a.z), "r"(a.w), "r"(b0), "r"(b1));
}

__device__ __forceinline__ int seg_of(const int* __restrict__ seg, int t) {
    int s = 0;
#pragma unroll
    for (int i = 1; i <= NA; i++) s += (seg[i] <= t) ? 1 : 0;
    return s < (NA - 1) ? s : (NA - 1);
}

// ===========================================================================
// Prepass A: x -> g_xa, RNE tf32, permuted to A-fragment layout
// block handles 16 rows x 128 cols; grid (32, 512)
// out block (m16, k8): lane (g,t4): {A[g][t4], A[g+8][t4], A[g][4+t4], A[g+8][4+t4]}
// ===========================================================================
__global__ __launch_bounds__(256) void perm_a_kernel(const float* __restrict__ x)
{
    __shared__ float sm[16][132];
    const int tid = threadIdx.x;
    const int k0 = blockIdx.x * 128;
    const int m0 = blockIdx.y * 16;
#pragma unroll
    for (int i = 0; i < 2; i++) {
        int idx = tid + i * 256;
        int row = idx >> 5;
        int c4  = idx & 31;
        float4 v = *reinterpret_cast<const float4*>(
            x + (size_t)(m0 + row) * D_IN + k0 + c4 * 4);
        *reinterpret_cast<float4*>(&sm[row][c4 * 4]) = v;
    }
    __syncthreads();
#pragma unroll
    for (int i = 0; i < 2; i++) {
        int idx = tid + i * 256;
        int k8 = idx >> 5;
        int ln = idx & 31;
        int g = ln >> 2, t4 = ln & 3;
        uint4 o;
        o.x = f2tf(sm[g][k8 * 8 + t4]);
        o.y = f2tf(sm[g + 8][k8 * 8 + t4]);
        o.z = f2tf(sm[g][k8 * 8 + 4 + t4]);
        o.w = f2tf(sm[g + 8][k8 * 8 + 4 + t4]);
        size_t off = ((size_t)blockIdx.y * 512 + blockIdx.x * 16 + k8) * 128 + ln * 4;
        *reinterpret_cast<uint4*>(g_xa + off) = o;
    }
}

// ===========================================================================
// Prepass B: W -> g_wb2, RNE tf32, permuted to B-fragment layout (2 k-steps packed)
// block handles 8 rows(n) x 256 cols(k); grid (16, 512)
// out block (n8, k16): lane (g,t4): {W[g][t4], W[g][4+t4], W[g][8+t4], W[g][12+t4]}
// ===========================================================================
__global__ __launch_bounds__(256) void perm_b_kernel(const float* __restrict__ w)
{
    __shared__ float sm[8][260];
    const int tid = threadIdx.x;
    const int k0 = blockIdx.x * 256;
    const int n0 = blockIdx.y * 8;
#pragma unroll
    for (int i = 0; i < 2; i++) {
        int idx = tid + i * 256;
        int row = idx >> 6;
        int c4  = idx & 63;
        float4 v = *reinterpret_cast<const float4*>(
            w + (size_t)(n0 + row) * D_IN + k0 + c4 * 4);
        *reinterpret_cast<float4*>(&sm[row][c4 * 4]) = v;
    }
    __syncthreads();
#pragma unroll
    for (int i = 0; i < 2; i++) {
        int idx = tid + i * 256;
        int k16 = idx >> 5;
        int ln = idx & 31;
        int g = ln >> 2, t4 = ln & 3;
        uint4 o;
        o.x = f2tf(sm[g][k16 * 16 + t4]);
        o.y = f2tf(sm[g][k16 * 16 + 4 + t4]);
        o.z = f2tf(sm[g][k16 * 16 + 8 + t4]);
        o.w = f2tf(sm[g][k16 * 16 + 12 + t4]);
        size_t off = ((size_t)blockIdx.y * 256 + blockIdx.x * 16 + k16) * 128 + ln * 4;
        *reinterpret_cast<uint4*>(g_wb2 + off) = o;
    }
}

// ===========================================================================
// LoRA H: H[t,r] = scaling[a_t] * sum_k x[t,k] wa[a_t,k,r]
// thread = (token 0..63, rq 0..3): 4 ranks per thread, float4 wa loads
// ===========================================================================
__global__ __launch_bounds__(256) void lora_h_kernel(
    const float* __restrict__ x, const float* __restrict__ wa,
    const float* __restrict__ scaling, const int* __restrict__ segment,
    const int* __restrict__ lora_ids)
{
    __shared__ float xs[64][68];
    const int tid = threadIdx.x;
    const int tl = tid >> 2;        // token 0..63
    const int rq = tid & 3;         // rank quad 0..3
    const int t0 = blockIdx.x * 64;
    const int t = t0 + tl;

    const int a = lora_ids[seg_of(segment, t)];
    float4 acc = make_float4(0.f, 0.f, 0.f, 0.f);

    for (int kc = 0; kc < D_IN; kc += 64) {
        __syncthreads();
#pragma unroll
        for (int j = 0; j < 4; j++) {
            int idx = tid + j * 256;
            int row = idx >> 4;
            int c4  = idx & 15;
            float4 v = *reinterpret_cast<const float4*>(
                x + (size_t)(t0 + row) * D_IN + kc + c4 * 4);
            *reinterpret_cast<float4*>(&xs[row][c4 * 4]) = v;
        }
        __syncthreads();

        const float* wp = wa + (size_t)a * D_IN * RANK + (size_t)kc * RANK + rq * 4;
#pragma unroll 8
        for (int k = 0; k < 64; k++) {
            float4 w = *reinterpret_cast<const float4*>(wp + k * RANK);
            float xv = xs[tl][k];
            acc.x = fmaf(xv, w.x, acc.x);
            acc.y = fmaf(xv, w.y, acc.y);
            acc.z = fmaf(xv, w.z, acc.z);
            acc.w = fmaf(xv, w.w, acc.w);
        }
    }
    const float sc = scaling[a];
    acc.x *= sc; acc.y *= sc; acc.z *= sc; acc.w *= sc;
    *reinterpret_cast<float4*>(g_Hs + (size_t)t * RANK + rq * 4) = acc;
    if (rq == 0) g_adp[t] = a;
}

// ===========================================================================
// Main GEMM: 128x128 tile, BK=32, 3-stage cp.async, pre-rounded permuted data,
// fused bias + LoRA epilogue. 8 warps (2m x 4n), warp tile 64x32.
// ===========================================================================
__global__ __launch_bounds__(256, 2) void fused_gemm_kernel(
    const float* __restrict__ bias, const float* __restrict__ wb,
    float* __restrict__ out)
{
    extern __shared__ float smem[];
    const uint32_t sa0 = smem_u32(smem);
    const uint32_t sb0 = sa0 + STAGES * A_STAGE_B;

    const int tid  = threadIdx.x;
    const int bn   = blockIdx.x;
    const int bm   = blockIdx.y;
    const int lane = tid & 31;
    const int warp = tid >> 5;
    const int wm   = warp & 1;
    const int wn   = warp >> 1;
    const int g    = lane >> 2;
    const int t4   = lane & 3;

    const int m16_base = bm * 8;    // 8 A-blocks per tile
    const int n8_base  = bn * 16;   // 16 B-blocks per tile

    float c[4][4][4];
#pragma unroll
    for (int mi = 0; mi < 4; mi++)
#pragma unroll
        for (int ni = 0; ni < 4; ni++)
#pragma unroll
            for (int q = 0; q < 4; q++) c[mi][ni][q] = 0.f;

    // ---- stage issue: 2048 16B chunks (A:1024, B:1024), 8 per thread ----
    auto issue_stage = [&](int kt, int s) {
#pragma unroll
        for (int i = 0; i < 4; i++) {           // A chunks
            int cch = tid + i * 256;
            int blk = cch >> 5, ln = cch & 31;
            int m16 = m16_base + (blk >> 2);
            int k8  = kt * 4 + (blk & 3);
            cp16(sa0 + s * A_STAGE_B + blk * 512 + ln * 16,
                 g_xa + ((size_t)m16 * 512 + k8) * 128 + ln * 4);
        }
#pragma unroll
        for (int i = 0; i < 4; i++) {           // B chunks
            int cch = tid + i * 256;
            int blk = cch >> 5, ln = cch & 31;
            int n8  = n8_base + (blk >> 1);
            int k16 = kt * 2 + (blk & 1);
            cp16(sb0 + s * B_STAGE_B + blk * 512 + ln * 16,
                 g_wb2 + ((size_t)n8 * 256 + k16) * 128 + ln * 4);
        }
    };

    issue_stage(0, 0); CP_COMMIT();
    issue_stage(1, 1); CP_COMMIT();

    int s_cur = 0;
    for (int kt = 0; kt < KTILES; kt++) {
        CP_WAIT1();
        __syncthreads();

        if (kt + 2 < KTILES) {
            int s_next = s_cur + 2;
            if (s_next >= STAGES) s_next -= STAGES;
            issue_stage(kt + 2, s_next);
        }
        CP_COMMIT();

        const uint32_t aS = sa0 + s_cur * A_STAGE_B + (wm * 4) * 4 * 512 + lane * 16;
        const uint32_t bS = sb0 + s_cur * B_STAGE_B + (wn * 4) * 2 * 512 + lane * 16;

#pragma unroll
        for (int kp = 0; kp < 2; kp++) {
            uint4 bfr[4];
#pragma unroll
            for (int ni = 0; ni < 4; ni++)
                bfr[ni] = lds128(bS + (ni * 2 + kp) * 512);
#pragma unroll
            for (int kkh = 0; kkh < 2; kkh++) {
                const int kk = kp * 2 + kkh;
                uint4 afr[4];
#pragma unroll
                for (int mi = 0; mi < 4; mi++)
                    afr[mi] = lds128(aS + (mi * 4 + kk) * 512);
#pragma unroll
                for (int mi = 0; mi < 4; mi++)
#pragma unroll
                    for (int ni = 0; ni < 4; ni++) {
                        if (kkh == 0)
                            mma_tf32(c[mi][ni], afr[mi], bfr[ni].x, bfr[ni].y);
                        else
                            mma_tf32(c[mi][ni], afr[mi], bfr[ni].z, bfr[ni].w);
                    }
            }
        }
        s_cur = s_cur + 1; if (s_cur >= STAGES) s_cur -= STAGES;
    }

    // ---------------- epilogue: bias + LoRA + store ----------------
    const int rbase = bm * BM + wm * 64;
    const int cbase = bn * BN + wn * 32;

    int trow[8], ta[8];
#pragma unroll
    for (int mi = 0; mi < 4; mi++)
#pragma unroll
        for (int hh = 0; hh < 2; hh++) {
            int t = rbase + mi * 16 + g + 8 * hh;
            trow[mi * 2 + hh] = t;
            ta[mi * 2 + hh] = g_adp[t];
        }
    bool uni = true;
#pragma unroll
    for (int q = 1; q < 8; q++) uni = uni && (ta[q] == ta[0]);

    if (uni) {
        const float* wbp = wb + (size_t)ta[0] * RANK * D_OUT;
#pragma unroll
        for (int ni = 0; ni < 4; ni++) {
            const int o = cbase + ni * 8 + t4 * 2;
            const float2 bv = *reinterpret_cast<const float2*>(bias + o);
            float2 wv[16];
#pragma unroll
            for (int j = 0; j < 16; j++)
                wv[j] = *reinterpret_cast<const float2*>(wbp + j * D_OUT + o);
#pragma unroll
            for (int mi = 0; mi < 4; mi++)
#pragma unroll
                for (int hh = 0; hh < 2; hh++) {
                    const int t = trow[mi * 2 + hh];
                    const float4* hp = reinterpret_cast<const float4*>(g_Hs + t * RANK);
                    float hreg[16];
                    *reinterpret_cast<float4*>(&hreg[0])  = hp[0];
                    *reinterpret_cast<float4*>(&hreg[4])  = hp[1];
                    *reinterpret_cast<float4*>(&hreg[8])  = hp[2];
                    *reinterpret_cast<float4*>(&hreg[12]) = hp[3];
                    float l0 = 0.f, l1 = 0.f;
#pragma unroll
                    for (int j = 0; j < 16; j++) {
                        l0 = fmaf(hreg[j], wv[j].x, l0);
                        l1 = fmaf(hreg[j], wv[j].y, l1);
                    }
                    float2 res;
                    res.x = c[mi][ni][2 * hh + 0] + bv.x + l0;
                    res.y = c[mi][ni][2 * hh + 1] + bv.y + l1;
                    *reinterpret_cast<float2*>(out + (size_t)t * D_OUT + o) = res;
                }
        }
    } else {
#pragma unroll
        for (int q = 0; q < 8; q++) {
            const int mi = q >> 1, hh = q & 1;
            const int t = trow[q];
            const float* wbp = wb + (size_t)ta[q] * RANK * D_OUT;
            const float4* hp = reinterpret_cast<const float4*>(g_Hs + t * RANK);
            float hreg[16];
            *reinterpret_cast<float4*>(&hreg[0])  = hp[0];
            *reinterpret_cast<float4*>(&hreg[4])  = hp[1];
            *reinterpret_cast<float4*>(&hreg[8])  = hp[2];
            *reinterpret_cast<float4*>(&hreg[12]) = hp[3];
#pragma unroll
            for (int ni = 0; ni < 4; ni++) {
                const int o = cbase + ni * 8 + t4 * 2;
                float l0 = bias[o], l1 = bias[o + 1];
#pragma unroll
                for (int j = 0; j < 16; j++) {
                    l0 = fmaf(hreg[j], __ldg(wbp + j * D_OUT + o), l0);
                    l1 = fmaf(hreg[j], __ldg(wbp + j * D_OUT + o + 1), l1);
                }
                float2 res;
                res.x = c[mi][ni][2 * hh + 0] + l0;
                res.y = c[mi][ni][2 * hh + 1] + l1;
                *reinterpret_cast<float2*>(out + (size_t)t * D_OUT + o) = res;
            }
        }
    }
}

// ===========================================================================
extern "C" void kernel_launch(void* const* d_in, const int* in_sizes, int n_in,
                              void* d_out, int out_size)
{
    (void)in_sizes; (void)n_in; (void)out_size;
    const float* x       = (const float*)d_in[0];
    const float* base_w  = (const float*)d_in[1];
    const float* base_b  = (const float*)d_in[2];
    const float* wa      = (const float*)d_in[3];
    const float* wb      = (const float*)d_in[4];
    const float* scaling = (const float*)d_in[5];
    const int*   segment = (const int*)d_in[6];
    const int*   lora_id = (const int*)d_in[7];
    float* out = (float*)d_out;

    perm_a_kernel<<<dim3(32, 512), 256>>>(x);
    perm_b_kernel<<<dim3(16, 512), 256>>>(base_w);
    lora_h_kernel<<<T_TOK / 64, 256>>>(x, wa, scaling, segment, lora_id);

    cudaFuncSetAttribute(fused_gemm_kernel,
                         cudaFuncAttributeMaxDynamicSharedMemorySize, SMEM_TOTAL);
    dim3 grid(D_OUT / BN, T_TOK / BM);   // (32, 64)
    fused_gemm_kernel<<<grid, 256, SMEM_TOTAL>>>(base_b, wb, out);
}

// round 5
// speedup vs baseline: 1.3522x; 1.1109x over previous
#include <cuda_runtime.h>
#include <cstdint>
#include <cstddef>

#define T_TOK 8192
#define D_IN  4096
#define D_OUT 4096
#define RANK  16
#define NA    8

// ---- GEMM tile config: CTA 128x128, 4 warps of 64x64, BK=32, 3 stages ----
#define BM 128
#define BN 128
#define BK 32
#define STAGES 3
#define KTILES (D_IN / BK)          // 128
#define A_STAGE_B 16384             // 32 blocks x 512B
#define B_STAGE_B 16384
#define SMEM_TOTAL (STAGES * (A_STAGE_B + B_STAGE_B))   // 98304

// ---- scratch (__device__ globals; no allocation allowed) ----
__device__ float g_xa[(size_t)T_TOK * D_IN];    // A-fragment order, tf32-rounded
__device__ float g_wb2[(size_t)D_OUT * D_IN];   // B-fragment order, tf32-rounded
__device__ float g_Hs[T_TOK * RANK];
__device__ int   g_adp[T_TOK];

// ===========================================================================
// helpers
// ===========================================================================
__device__ __forceinline__ uint32_t smem_u32(const void* p) {
    return (uint32_t)__cvta_generic_to_shared(p);
}
__device__ __forceinline__ uint32_t f2tf(float f) {
    uint32_t u;
    asm("cvt.rna.tf32.f32 %0, %1;" : "=r"(u) : "f"(f));
    return u;
}
__device__ __forceinline__ void cp16(uint32_t dst, const void* src) {
    asm volatile("cp.async.cg.shared.global [%0], [%1], 16;\n" ::"r"(dst), "l"(src));
}
#define CP_COMMIT() asm volatile("cp.async.commit_group;\n")
#define CP_WAIT1()  asm volatile("cp.async.wait_group 1;\n")

__device__ __forceinline__ uint4 lds128(uint32_t a) {
    uint4 v;
    asm volatile("ld.shared.v4.b32 {%0,%1,%2,%3}, [%4];"
                 : "=r"(v.x), "=r"(v.y), "=r"(v.z), "=r"(v.w) : "r"(a));
    return v;
}
__device__ __forceinline__ void mma_tf32(float* c, const uint4& a, uint32_t b0, uint32_t b1) {
    asm volatile(
        "mma.sync.aligned.m16n8k8.row.col.f32.tf32.tf32.f32 "
        "{%0,%1,%2,%3},{%4,%5,%6,%7},{%8,%9},{%0,%1,%2,%3};\n"
        : "+f"(c[0]), "+f"(c[1]), "+f"(c[2]), "+f"(c[3])
        : "r"(a.x), "r"(a.y), "r"(a.z), "r"(a.w), "r"(b0), "r"(b1));
}

__device__ __forceinline__ int seg_of(const int* __restrict__ seg, int t) {
    int s = 0;
#pragma unroll
    for (int i = 1; i <= NA; i++) s += (seg[i] <= t) ? 1 : 0;
    return s < (NA - 1) ? s : (NA - 1);
}

// ===========================================================================
// Prepass A: x -> g_xa, RNE tf32, A-fragment layout [m16][k8][lane][4]
// ===========================================================================
__global__ __launch_bounds__(256) void perm_a_kernel(const float* __restrict__ x)
{
    __shared__ float sm[16][132];
    const int tid = threadIdx.x;
    const int k0 = blockIdx.x * 128;
    const int m0 = blockIdx.y * 16;
#pragma unroll
    for (int i = 0; i < 2; i++) {
        int idx = tid + i * 256;
        int row = idx >> 5;
        int c4  = idx & 31;
        float4 v = *reinterpret_cast<const float4*>(
            x + (size_t)(m0 + row) * D_IN + k0 + c4 * 4);
        *reinterpret_cast<float4*>(&sm[row][c4 * 4]) = v;
    }
    __syncthreads();
#pragma unroll
    for (int i = 0; i < 2; i++) {
        int idx = tid + i * 256;
        int k8 = idx >> 5;
        int ln = idx & 31;
        int g = ln >> 2, t4 = ln & 3;
        uint4 o;
        o.x = f2tf(sm[g][k8 * 8 + t4]);
        o.y = f2tf(sm[g + 8][k8 * 8 + t4]);
        o.z = f2tf(sm[g][k8 * 8 + 4 + t4]);
        o.w = f2tf(sm[g + 8][k8 * 8 + 4 + t4]);
        size_t off = ((size_t)blockIdx.y * 512 + blockIdx.x * 16 + k8) * 128 + ln * 4;
        *reinterpret_cast<uint4*>(g_xa + off) = o;
    }
}

// ===========================================================================
// Prepass B: W -> g_wb2, RNE tf32, B-fragment layout [n8][k16][lane][4]
// ===========================================================================
__global__ __launch_bounds__(256) void perm_b_kernel(const float* __restrict__ w)
{
    __shared__ float sm[8][260];
    const int tid = threadIdx.x;
    const int k0 = blockIdx.x * 256;
    const int n0 = blockIdx.y * 8;
#pragma unroll
    for (int i = 0; i < 2; i++) {
        int idx = tid + i * 256;
        int row = idx >> 6;
        int c4  = idx & 63;
        float4 v = *reinterpret_cast<const float4*>(
            w + (size_t)(n0 + row) * D_IN + k0 + c4 * 4);
        *reinterpret_cast<float4*>(&sm[row][c4 * 4]) = v;
    }
    __syncthreads();
#pragma unroll
    for (int i = 0; i < 2; i++) {
        int idx = tid + i * 256;
        int k16 = idx >> 5;
        int ln = idx & 31;
        int g = ln >> 2, t4 = ln & 3;
        uint4 o;
        o.x = f2tf(sm[g][k16 * 16 + t4]);
        o.y = f2tf(sm[g][k16 * 16 + 4 + t4]);
        o.z = f2tf(sm[g][k16 * 16 + 8 + t4]);
        o.w = f2tf(sm[g][k16 * 16 + 12 + t4]);
        size_t off = ((size_t)blockIdx.y * 256 + blockIdx.x * 16 + k16) * 128 + ln * 4;
        *reinterpret_cast<uint4*>(g_wb2 + off) = o;
    }
}

// ===========================================================================
// LoRA H
// ===========================================================================
__global__ __launch_bounds__(256) void lora_h_kernel(
    const float* __restrict__ x, const float* __restrict__ wa,
    const float* __restrict__ scaling, const int* __restrict__ segment,
    const int* __restrict__ lora_ids)
{
    __shared__ float xs[64][68];
    const int tid = threadIdx.x;
    const int tl = tid >> 2;
    const int rq = tid & 3;
    const int t0 = blockIdx.x * 64;
    const int t = t0 + tl;

    const int a = lora_ids[seg_of(segment, t)];
    float4 acc = make_float4(0.f, 0.f, 0.f, 0.f);

    for (int kc = 0; kc < D_IN; kc += 64) {
        __syncthreads();
#pragma unroll
        for (int j = 0; j < 4; j++) {
            int idx = tid + j * 256;
            int row = idx >> 4;
            int c4  = idx & 15;
            float4 v = *reinterpret_cast<const float4*>(
                x + (size_t)(t0 + row) * D_IN + kc + c4 * 4);
            *reinterpret_cast<float4*>(&xs[row][c4 * 4]) = v;
        }
        __syncthreads();

        const float* wp = wa + (size_t)a * D_IN * RANK + (size_t)kc * RANK + rq * 4;
#pragma unroll 8
        for (int k = 0; k < 64; k++) {
            float4 w = *reinterpret_cast<const float4*>(wp + k * RANK);
            float xv = xs[tl][k];
            acc.x = fmaf(xv, w.x, acc.x);
            acc.y = fmaf(xv, w.y, acc.y);
            acc.z = fmaf(xv, w.z, acc.z);
            acc.w = fmaf(xv, w.w, acc.w);
        }
    }
    const float sc = scaling[a];
    acc.x *= sc; acc.y *= sc; acc.z *= sc; acc.w *= sc;
    *reinterpret_cast<float4*>(g_Hs + (size_t)t * RANK + rq * 4) = acc;
    if (rq == 0) g_adp[t] = a;
}

// ===========================================================================
// Main GEMM: CTA 128x128, 4 warps (2x2) of 64x64, 3-stage cp.async,
// hoisted address math, fused bias + LoRA epilogue.
// ===========================================================================
__global__ __launch_bounds__(128, 2) void fused_gemm_kernel(
    const float* __restrict__ bias, const float* __restrict__ wb,
    float* __restrict__ out)
{
    extern __shared__ float smem[];
    const uint32_t sa0 = smem_u32(smem);
    const uint32_t sb0 = sa0 + STAGES * A_STAGE_B;

    const int tid  = threadIdx.x;
    const int bn   = blockIdx.x;
    const int bm   = blockIdx.y;
    const int lane = tid & 31;
    const int warp = tid >> 5;     // 0..3
    const int wm   = warp & 1;
    const int wn   = warp >> 1;
    const int g    = lane >> 2;
    const int t4   = lane & 3;

    // ---- hoisted cp.async addressing (8 A-chunks + 8 B-chunks per thread) ----
    // A stage: 32 blocks (m16_local 0..7 x k8i 0..3) x 512B. kt advance: +512 floats
    // B stage: 32 blocks (n8_local 0..15 x k16i 0..1) x 512B. kt advance: +256 floats
    int aoff[8], dAo[8], boff[8], dBo[8];
#pragma unroll
    for (int i = 0; i < 8; i++) {
        int cch = tid + i * 128;          // 0..1023
        int blk = cch >> 5, ln = cch & 31;
        {
            int m16 = bm * 8 + (blk >> 2);
            int k8i = blk & 3;
            aoff[i] = (m16 * 512 + k8i) * 128 + ln * 4;
            dAo[i]  = blk * 512 + ln * 16;
        }
        {
            int n8  = bn * 16 + (blk >> 1);
            int k16i = blk & 1;
            boff[i] = (n8 * 256 + k16i) * 128 + ln * 4;
            dBo[i]  = blk * 512 + ln * 16;
        }
    }

    float c[4][8][4];
#pragma unroll
    for (int mi = 0; mi < 4; mi++)
#pragma unroll
        for (int ni = 0; ni < 8; ni++)
#pragma unroll
            for (int q = 0; q < 4; q++) c[mi][ni][q] = 0.f;

    auto issue_stage = [&](int kt, int s) {
        const uint32_t dA = sa0 + s * A_STAGE_B;
        const uint32_t dB = sb0 + s * B_STAGE_B;
        const int ka = kt * 512, kb = kt * 256;
#pragma unroll
        for (int i = 0; i < 8; i++)
            cp16(dA + dAo[i], g_xa + aoff[i] + ka);
#pragma unroll
        for (int i = 0; i < 8; i++)
            cp16(dB + dBo[i], g_wb2 + boff[i] + kb);
    };

    issue_stage(0, 0); CP_COMMIT();
    issue_stage(1, 1); CP_COMMIT();

    int s_cur = 0;
    for (int kt = 0; kt < KTILES; kt++) {
        CP_WAIT1();
        __syncthreads();

        if (kt + 2 < KTILES) {
            int s_next = s_cur + 2;
            if (s_next >= STAGES) s_next -= STAGES;
            issue_stage(kt + 2, s_next);
        }
        CP_COMMIT();

        const uint32_t aS = sa0 + s_cur * A_STAGE_B + wm * 8192 + lane * 16;
        const uint32_t bS = sb0 + s_cur * B_STAGE_B + wn * 8192 + lane * 16;

#pragma unroll
        for (int kp = 0; kp < 2; kp++) {
            uint4 bfr[8];
#pragma unroll
            for (int ni = 0; ni < 8; ni++)
                bfr[ni] = lds128(bS + (ni * 2 + kp) * 512);
#pragma unroll
            for (int kkh = 0; kkh < 2; kkh++) {
                const int kk = kp * 2 + kkh;
                uint4 afr[4];
#pragma unroll
                for (int mi = 0; mi < 4; mi++)
                    afr[mi] = lds128(aS + (mi * 4 + kk) * 512);
#pragma unroll
                for (int mi = 0; mi < 4; mi++)
#pragma unroll
                    for (int ni = 0; ni < 8; ni++) {
                        if (kkh == 0)
                            mma_tf32(c[mi][ni], afr[mi], bfr[ni].x, bfr[ni].y);
                        else
                            mma_tf32(c[mi][ni], afr[mi], bfr[ni].z, bfr[ni].w);
                    }
            }
        }
        s_cur = s_cur + 1; if (s_cur >= STAGES) s_cur -= STAGES;
    }

    // ---------------- epilogue: bias + LoRA + store ----------------
    const int rbase = bm * BM + wm * 64;
    const int cbase = bn * BN + wn * 64;

    int trow[8], ta[8];
#pragma unroll
    for (int mi = 0; mi < 4; mi++)
#pragma unroll
        for (int hh = 0; hh < 2; hh++) {
            int t = rbase + mi * 16 + g + 8 * hh;
            trow[mi * 2 + hh] = t;
            ta[mi * 2 + hh] = g_adp[t];
        }
    bool uni = true;
#pragma unroll
    for (int q = 1; q < 8; q++) uni = uni && (ta[q] == ta[0]);

    if (uni) {
        const float* wbp = wb + (size_t)ta[0] * RANK * D_OUT;
#pragma unroll
        for (int ni = 0; ni < 8; ni++) {
            const int o = cbase + ni * 8 + t4 * 2;
            const float2 bv = *reinterpret_cast<const float2*>(bias + o);
            float2 wv[16];
#pragma unroll
            for (int j = 0; j < 16; j++)
                wv[j] = *reinterpret_cast<const float2*>(wbp + j * D_OUT + o);
#pragma unroll
            for (int mi = 0; mi < 4; mi++)
#pragma unroll
                for (int hh = 0; hh < 2; hh++) {
                    const int t = trow[mi * 2 + hh];
                    const float4* hp = reinterpret_cast<const float4*>(g_Hs + t * RANK);
                    float hreg[16];
                    *reinterpret_cast<float4*>(&hreg[0])  = hp[0];
                    *reinterpret_cast<float4*>(&hreg[4])  = hp[1];
                    *reinterpret_cast<float4*>(&hreg[8])  = hp[2];
                    *reinterpret_cast<float4*>(&hreg[12]) = hp[3];
                    float l0 = 0.f, l1 = 0.f;
#pragma unroll
                    for (int j = 0; j < 16; j++) {
                        l0 = fmaf(hreg[j], wv[j].x, l0);
                        l1 = fmaf(hreg[j], wv[j].y, l1);
                    }
                    float2 res;
                    res.x = c[mi][ni][2 * hh + 0] + bv.x + l0;
                    res.y = c[mi][ni][2 * hh + 1] + bv.y + l1;
                    *reinterpret_cast<float2*>(out + (size_t)t * D_OUT + o) = res;
                }
        }
    } else {
#pragma unroll
        for (int q = 0; q < 8; q++) {
            const int mi = q >> 1, hh = q & 1;
            const int t = trow[q];
            const float* wbp = wb + (size_t)ta[q] * RANK * D_OUT;
            const float4* hp = reinterpret_cast<const float4*>(g_Hs + t * RANK);
            float hreg[16];
            *reinterpret_cast<float4*>(&hreg[0])  = hp[0];
            *reinterpret_cast<float4*>(&hreg[4])  = hp[1];
            *reinterpret_cast<float4*>(&hreg[8])  = hp[2];
            *reinterpret_cast<float4*>(&hreg[12]) = hp[3];
#pragma unroll
            for (int ni = 0; ni < 8; ni++) {
                const int o = cbase + ni * 8 + t4 * 2;
                float l0 = bias[o], l1 = bias[o + 1];
#pragma unroll
                for (int j = 0; j < 16; j++) {
                    l0 = fmaf(hreg[j], __ldg(wbp + j * D_OUT + o), l0);
                    l1 = fmaf(hreg[j], __ldg(wbp + j * D_OUT + o + 1), l1);
                }
                float2 res;
                res.x = c[mi][ni][2 * hh + 0] + l0;
                res.y = c[mi][ni][2 * hh + 1] + l1;
                *reinterpret_cast<float2*>(out + (size_t)t * D_OUT + o) = res;
            }
        }
    }
}

// ===========================================================================
extern "C" void kernel_launch(void* const* d_in, const int* in_sizes, int n_in,
                              void* d_out, int out_size)
{
    (void)in_sizes; (void)n_in; (void)out_size;
    const float* x       = (const float*)d_in[0];
    const float* base_w  = (const float*)d_in[1];
    const float* base_b  = (const float*)d_in[2];
    const float* wa      = (const float*)d_in[3];
    const float* wb      = (const float*)d_in[4];
    const float* scaling = (const float*)d_in[5];
    const int*   segment = (const int*)d_in[6];
    const int*   lora_id = (const int*)d_in[7];
    float* out = (float*)d_out;

    perm_a_kernel<<<dim3(32, 512), 256>>>(x);
    perm_b_kernel<<<dim3(16, 512), 256>>>(base_w);
    lora_h_kernel<<<T_TOK / 64, 256>>>(x, wa, scaling, segment, lora_id);

    cudaFuncSetAttribute(fused_gemm_kernel,
                         cudaFuncAttributeMaxDynamicSharedMemorySize, SMEM_TOTAL);
    dim3 grid(D_OUT / BN, T_TOK / BM);   // (32, 64)
    fused_gemm_kernel<<<grid, 128, SMEM_TOTAL>>>(base_b, wb, out);
}

// round 6
// speedup vs baseline: 1.6651x; 1.2314x over previous
#include <cuda_runtime.h>
#include <cstdint>
#include <cstddef>

#define T_TOK 8192
#define D_IN  4096
#define D_OUT 4096
#define RANK  16
#define NA    8

// ---- GEMM tile config: CTA 128x128, 4 warps of 64x64, BK=32, 3 stages ----
#define BM 128
#define BN 128
#define BK 32
#define STAGES 3
#define KTILES (D_IN / BK)          // 128
#define A_STAGE_B 16384
#define B_STAGE_B 16384
#define SMEM_TOTAL (STAGES * (A_STAGE_B + B_STAGE_B))   // 98304

// ---- scratch (__device__ globals; no allocation allowed) ----
__device__ float g_xa[(size_t)T_TOK * D_IN];    // A-fragment order, tf32-rounded
__device__ float g_wb2[(size_t)D_OUT * D_IN];   // B-fragment order, tf32-rounded
__device__ float g_Hs[T_TOK * RANK];
__device__ int   g_adp[T_TOK];

// ===========================================================================
// helpers
// ===========================================================================
__device__ __forceinline__ uint32_t smem_u32(const void* p) {
    return (uint32_t)__cvta_generic_to_shared(p);
}
__device__ __forceinline__ uint32_t f2tf(float f) {
    uint32_t u;
    asm("cvt.rna.tf32.f32 %0, %1;" : "=r"(u) : "f"(f));
    return u;
}
__device__ __forceinline__ void cp16(uint32_t dst, const void* src) {
    asm volatile("cp.async.cg.shared.global [%0], [%1], 16;\n" ::"r"(dst), "l"(src));
}
#define CP_COMMIT() asm volatile("cp.async.commit_group;\n")
#define CP_WAIT1()  asm volatile("cp.async.wait_group 1;\n")

__device__ __forceinline__ uint4 lds128(uint32_t a) {
    uint4 v;
    asm volatile("ld.shared.v4.b32 {%0,%1,%2,%3}, [%4];"
                 : "=r"(v.x), "=r"(v.y), "=r"(v.z), "=r"(v.w) : "r"(a));
    return v;
}
__device__ __forceinline__ void mma_tf32(float* c, const uint4& a, uint32_t b0, uint32_t b1) {
    asm volatile(
        "mma.sync.aligned.m16n8k8.row.col.f32.tf32.tf32.f32 "
        "{%0,%1,%2,%3},{%4,%5,%6,%7},{%8,%9},{%0,%1,%2,%3};\n"
        : "+f"(c[0]), "+f"(c[1]), "+f"(c[2]), "+f"(c[3])
        : "r"(a.x), "r"(a.y), "r"(a.z), "r"(a.w), "r"(b0), "r"(b1));
}

__device__ __forceinline__ int seg_of(const int* __restrict__ seg, int t) {
    int s = 0;
#pragma unroll
    for (int i = 1; i <= NA; i++) s += (seg[i] <= t) ? 1 : 0;
    return s < (NA - 1) ? s : (NA - 1);
}

// ===========================================================================
// Prepass A: x -> g_xa, RNE tf32, A-fragment layout [m16][k8][lane][4]
// ===========================================================================
__global__ __launch_bounds__(256) void perm_a_kernel(const float* __restrict__ x)
{
    __shared__ float sm[16][132];
    const int tid = threadIdx.x;
    const int k0 = blockIdx.x * 128;
    const int m0 = blockIdx.y * 16;
#pragma unroll
    for (int i = 0; i < 2; i++) {
        int idx = tid + i * 256;
        int row = idx >> 5;
        int c4  = idx & 31;
        float4 v = *reinterpret_cast<const float4*>(
            x + (size_t)(m0 + row) * D_IN + k0 + c4 * 4);
        *reinterpret_cast<float4*>(&sm[row][c4 * 4]) = v;
    }
    __syncthreads();
#pragma unroll
    for (int i = 0; i < 2; i++) {
        int idx = tid + i * 256;
        int k8 = idx >> 5;
        int ln = idx & 31;
        int g = ln >> 2, t4 = ln & 3;
        uint4 o;
        o.x = f2tf(sm[g][k8 * 8 + t4]);
        o.y = f2tf(sm[g + 8][k8 * 8 + t4]);
        o.z = f2tf(sm[g][k8 * 8 + 4 + t4]);
        o.w = f2tf(sm[g + 8][k8 * 8 + 4 + t4]);
        size_t off = ((size_t)blockIdx.y * 512 + blockIdx.x * 16 + k8) * 128 + ln * 4;
        *reinterpret_cast<uint4*>(g_xa + off) = o;
    }
}

// ===========================================================================
// Prepass B: W -> g_wb2, RNE tf32, B-fragment layout [n8][k16][lane][4]
// ===========================================================================
__global__ __launch_bounds__(256) void perm_b_kernel(const float* __restrict__ w)
{
    __shared__ float sm[8][260];
    const int tid = threadIdx.x;
    const int k0 = blockIdx.x * 256;
    const int n0 = blockIdx.y * 8;
#pragma unroll
    for (int i = 0; i < 2; i++) {
        int idx = tid + i * 256;
        int row = idx >> 6;
        int c4  = idx & 63;
        float4 v = *reinterpret_cast<const float4*>(
            w + (size_t)(n0 + row) * D_IN + k0 + c4 * 4);
        *reinterpret_cast<float4*>(&sm[row][c4 * 4]) = v;
    }
    __syncthreads();
#pragma unroll
    for (int i = 0; i < 2; i++) {
        int idx = tid + i * 256;
        int k16 = idx >> 5;
        int ln = idx & 31;
        int g = ln >> 2, t4 = ln & 3;
        uint4 o;
        o.x = f2tf(sm[g][k16 * 16 + t4]);
        o.y = f2tf(sm[g][k16 * 16 + 4 + t4]);
        o.z = f2tf(sm[g][k16 * 16 + 8 + t4]);
        o.w = f2tf(sm[g][k16 * 16 + 12 + t4]);
        size_t off = ((size_t)blockIdx.y * 256 + blockIdx.x * 16 + k16) * 128 + ln * 4;
        *reinterpret_cast<uint4*>(g_wb2 + off) = o;
    }
}

// ===========================================================================
// LoRA H: H[t,r] = scaling[a_t] * sum_k x[t,k] wa[a_t,k,r]
// smem-staged wa chunk (4KB per 64-k chunk) -> inner loop is pure LDS+FFMA
// ===========================================================================
__global__ __launch_bounds__(256) void lora_h_kernel(
    const float* __restrict__ x, const float* __restrict__ wa,
    const float* __restrict__ scaling, const int* __restrict__ segment,
    const int* __restrict__ lora_ids)
{
    __shared__ float xs[64][68];
    __shared__ float4 was[64][4];      // wa chunk [k][rq]: 64 x 16 floats
    const int tid = threadIdx.x;
    const int tl = tid >> 2;           // token 0..63
    const int rq = tid & 3;            // rank quad
    const int t0 = blockIdx.x * 64;
    const int t = t0 + tl;

    const int a = lora_ids[seg_of(segment, t)];
    // segments are contiguous: endpoints equal => whole block uniform
    const int a_first = lora_ids[seg_of(segment, t0)];
    const int a_last  = lora_ids[seg_of(segment, t0 + 63)];
    const bool blk_uni = (a_first == a_last);

    float4 acc = make_float4(0.f, 0.f, 0.f, 0.f);

    for (int kc = 0; kc < D_IN; kc += 64) {
        __syncthreads();
#pragma unroll
        for (int j = 0; j < 4; j++) {
            int idx = tid + j * 256;
            int row = idx >> 4;
            int c4  = idx & 15;
            float4 v = *reinterpret_cast<const float4*>(
                x + (size_t)(t0 + row) * D_IN + kc + c4 * 4);
            *reinterpret_cast<float4*>(&xs[row][c4 * 4]) = v;
        }
        if (blk_uni) {
            // stage wa[a_first][kc..kc+63][0..15]: 1024 floats, 4 per thread
            int k = tid >> 2;          // 0..63
            int q = tid & 3;           // 0..3
            was[k][q] = *reinterpret_cast<const float4*>(
                wa + ((size_t)a_first * D_IN + kc + k) * RANK + q * 4);
        }
        __syncthreads();

        if (blk_uni) {
#pragma unroll 8
            for (int k = 0; k < 64; k++) {
                float4 w = was[k][rq];
                float xv = xs[tl][k];
                acc.x = fmaf(xv, w.x, acc.x);
                acc.y = fmaf(xv, w.y, acc.y);
                acc.z = fmaf(xv, w.z, acc.z);
                acc.w = fmaf(xv, w.w, acc.w);
            }
        } else {
            const float* wp = wa + (size_t)a * D_IN * RANK + (size_t)kc * RANK + rq * 4;
#pragma unroll 8
            for (int k = 0; k < 64; k++) {
                float4 w = *reinterpret_cast<const float4*>(wp + k * RANK);
                float xv = xs[tl][k];
                acc.x = fmaf(xv, w.x, acc.x);
                acc.y = fmaf(xv, w.y, acc.y);
                acc.z = fmaf(xv, w.z, acc.z);
                acc.w = fmaf(xv, w.w, acc.w);
            }
        }
    }
    const float sc = scaling[a];
    acc.x *= sc; acc.y *= sc; acc.z *= sc; acc.w *= sc;
    *reinterpret_cast<float4*>(g_Hs + (size_t)t * RANK + rq * 4) = acc;
    if (rq == 0) g_adp[t] = a;
}

// ===========================================================================
// Main GEMM: CTA 128x128, 4 warps (2x2) of 64x64, 3-stage cp.async,
// hoisted address math, fused bias + LoRA epilogue.  (unchanged from R5)
// ===========================================================================
__global__ __launch_bounds__(128, 2) void fused_gemm_kernel(
    const float* __restrict__ bias, const float* __restrict__ wb,
    float* __restrict__ out)
{
    extern __shared__ float smem[];
    const uint32_t sa0 = smem_u32(smem);
    const uint32_t sb0 = sa0 + STAGES * A_STAGE_B;

    const int tid  = threadIdx.x;
    const int bn   = blockIdx.x;
    const int bm   = blockIdx.y;
    const int lane = tid & 31;
    const int warp = tid >> 5;
    const int wm   = warp & 1;
    const int wn   = warp >> 1;
    const int g    = lane >> 2;
    const int t4   = lane & 3;

    int aoff[8], dAo[8], boff[8], dBo[8];
#pragma unroll
    for (int i = 0; i < 8; i++) {
        int cch = tid + i * 128;
        int blk = cch >> 5, ln = cch & 31;
        {
            int m16 = bm * 8 + (blk >> 2);
            int k8i = blk & 3;
            aoff[i] = (m16 * 512 + k8i) * 128 + ln * 4;
            dAo[i]  = blk * 512 + ln * 16;
        }
        {
            int n8  = bn * 16 + (blk >> 1);
            int k16i = blk & 1;
            boff[i] = (n8 * 256 + k16i) * 128 + ln * 4;
            dBo[i]  = blk * 512 + ln * 16;
        }
    }

    float c[4][8][4];
#pragma unroll
    for (int mi = 0; mi < 4; mi++)
#pragma unroll
        for (int ni = 0; ni < 8; ni++)
#pragma unroll
            for (int q = 0; q < 4; q++) c[mi][ni][q] = 0.f;

    auto issue_stage = [&](int kt, int s) {
        const uint32_t dA = sa0 + s * A_STAGE_B;
        const uint32_t dB = sb0 + s * B_STAGE_B;
        const int ka = kt * 512, kb = kt * 256;
#pragma unroll
        for (int i = 0; i < 8; i++)
            cp16(dA + dAo[i], g_xa + aoff[i] + ka);
#pragma unroll
        for (int i = 0; i < 8; i++)
            cp16(dB + dBo[i], g_wb2 + boff[i] + kb);
    };

    issue_stage(0, 0); CP_COMMIT();
    issue_stage(1, 1); CP_COMMIT();

    int s_cur = 0;
    for (int kt = 0; kt < KTILES; kt++) {
        CP_WAIT1();
        __syncthreads();

        if (kt + 2 < KTILES) {
            int s_next = s_cur + 2;
            if (s_next >= STAGES) s_next -= STAGES;
            issue_stage(kt + 2, s_next);
        }
        CP_COMMIT();

        const uint32_t aS = sa0 + s_cur * A_STAGE_B + wm * 8192 + lane * 16;
        const uint32_t bS = sb0 + s_cur * B_STAGE_B + wn * 8192 + lane * 16;

#pragma unroll
        for (int kp = 0; kp < 2; kp++) {
            uint4 bfr[8];
#pragma unroll
            for (int ni = 0; ni < 8; ni++)
                bfr[ni] = lds128(bS + (ni * 2 + kp) * 512);
#pragma unroll
            for (int kkh = 0; kkh < 2; kkh++) {
                const int kk = kp * 2 + kkh;
                uint4 afr[4];
#pragma unroll
                for (int mi = 0; mi < 4; mi++)
                    afr[mi] = lds128(aS + (mi * 4 + kk) * 512);
#pragma unroll
                for (int mi = 0; mi < 4; mi++)
#pragma unroll
                    for (int ni = 0; ni < 8; ni++) {
                        if (kkh == 0)
                            mma_tf32(c[mi][ni], afr[mi], bfr[ni].x, bfr[ni].y);
                        else
                            mma_tf32(c[mi][ni], afr[mi], bfr[ni].z, bfr[ni].w);
                    }
            }
        }
        s_cur = s_cur + 1; if (s_cur >= STAGES) s_cur -= STAGES;
    }

    // ---------------- epilogue: bias + LoRA + store ----------------
    const int rbase = bm * BM + wm * 64;
    const int cbase = bn * BN + wn * 64;

    int trow[8], ta[8];
#pragma unroll
    for (int mi = 0; mi < 4; mi++)
#pragma unroll
        for (int hh = 0; hh < 2; hh++) {
            int t = rbase + mi * 16 + g + 8 * hh;
            trow[mi * 2 + hh] = t;
            ta[mi * 2 + hh] = g_adp[t];
        }
    bool uni = true;
#pragma unroll
    for (int q = 1; q < 8; q++) uni = uni && (ta[q] == ta[0]);

    if (uni) {
        const float* wbp = wb + (size_t)ta[0] * RANK * D_OUT;
#pragma unroll
        for (int ni = 0; ni < 8; ni++) {
            const int o = cbase + ni * 8 + t4 * 2;
            const float2 bv = *reinterpret_cast<const float2*>(bias + o);
            float2 wv[16];
#pragma unroll
            for (int j = 0; j < 16; j++)
                wv[j] = *reinterpret_cast<const float2*>(wbp + j * D_OUT + o);
#pragma unroll
            for (int mi = 0; mi < 4; mi++)
#pragma unroll
                for (int hh = 0; hh < 2; hh++) {
                    const int t = trow[mi * 2 + hh];
                    const float4* hp = reinterpret_cast<const float4*>(g_Hs + t * RANK);
                    float hreg[16];
                    *reinterpret_cast<float4*>(&hreg[0])  = hp[0];
                    *reinterpret_cast<float4*>(&hreg[4])  = hp[1];
                    *reinterpret_cast<float4*>(&hreg[8])  = hp[2];
                    *reinterpret_cast<float4*>(&hreg[12]) = hp[3];
                    float l0 = 0.f, l1 = 0.f;
#pragma unroll
                    for (int j = 0; j < 16; j++) {
                        l0 = fmaf(hreg[j], wv[j].x, l0);
                        l1 = fmaf(hreg[j], wv[j].y, l1);
                    }
                    float2 res;
                    res.x = c[mi][ni][2 * hh + 0] + bv.x + l0;
                    res.y = c[mi][ni][2 * hh + 1] + bv.y + l1;
                    *reinterpret_cast<float2*>(out + (size_t)t * D_OUT + o) = res;
                }
        }
    } else {
#pragma unroll
        for (int q = 0; q < 8; q++) {
            const int mi = q >> 1, hh = q & 1;
            const int t = trow[q];
            const float* wbp = wb + (size_t)ta[q] * RANK * D_OUT;
            const float4* hp = reinterpret_cast<const float4*>(g_Hs + t * RANK);
            float hreg[16];
            *reinterpret_cast<float4*>(&hreg[0])  = hp[0];
            *reinterpret_cast<float4*>(&hreg[4])  = hp[1];
            *reinterpret_cast<float4*>(&hreg[8])  = hp[2];
            *reinterpret_cast<float4*>(&hreg[12]) = hp[3];
#pragma unroll
            for (int ni = 0; ni < 8; ni++) {
                const int o = cbase + ni * 8 + t4 * 2;
                float l0 = bias[o], l1 = bias[o + 1];
#pragma unroll
                for (int j = 0; j < 16; j++) {
                    l0 = fmaf(hreg[j], __ldg(wbp + j * D_OUT + o), l0);
                    l1 = fmaf(hreg[j], __ldg(wbp + j * D_OUT + o + 1), l1);
                }
                float2 res;
                res.x = c[mi][ni][2 * hh + 0] + l0;
                res.y = c[mi][ni][2 * hh + 1] + l1;
                *reinterpret_cast<float2*>(out + (size_t)t * D_OUT + o) = res;
            }
        }
    }
}

// ===========================================================================
extern "C" void kernel_launch(void* const* d_in, const int* in_sizes, int n_in,
                              void* d_out, int out_size)
{
    (void)in_sizes; (void)n_in; (void)out_size;
    const float* x       = (const float*)d_in[0];
    const float* base_w  = (const float*)d_in[1];
    const float* base_b  = (const float*)d_in[2];
    const float* wa      = (const float*)d_in[3];
    const float* wb      = (const float*)d_in[4];
    const float* scaling = (const float*)d_in[5];
    const int*   segment = (const int*)d_in[6];
    const int*   lora_id = (const int*)d_in[7];
    float* out = (float*)d_out;

    // static side streams + events for graph-parallel prepasses
    static cudaStream_t s1 = nullptr, s2 = nullptr;
    static cudaEvent_t e_fork = nullptr, e1 = nullptr, e2 = nullptr;
    static int inited = 0;
    if (!inited) {
        cudaStreamCreateWithFlags(&s1, cudaStreamNonBlocking);
        cudaStreamCreateWithFlags(&s2, cudaStreamNonBlocking);
        cudaEventCreateWithFlags(&e_fork, cudaEventDisableTiming);
        cudaEventCreateWithFlags(&e1, cudaEventDisableTiming);
        cudaEventCreateWithFlags(&e2, cudaEventDisableTiming);
        cudaFuncSetAttribute(fused_gemm_kernel,
                             cudaFuncAttributeMaxDynamicSharedMemorySize, SMEM_TOTAL);
        inited = 1;
    }

    // capture-legal fork/join: main -> {s1: perm_b, s2: lora_h}, main: perm_a
    cudaStream_t main_s = 0;   // harness launches us on the capture (legacy) stream
    cudaEventRecord(e_fork, main_s);
    cudaStreamWaitEvent(s1, e_fork, 0);
    cudaStreamWaitEvent(s2, e_fork, 0);

    perm_a_kernel<<<dim3(32, 512), 256, 0, main_s>>>(x);
    perm_b_kernel<<<dim3(16, 512), 256, 0, s1>>>(base_w);
    lora_h_kernel<<<T_TOK / 64, 256, 0, s2>>>(x, wa, scaling, segment, lora_id);

    cudaEventRecord(e1, s1);
    cudaEventRecord(e2, s2);
    cudaStreamWaitEvent(main_s, e1, 0);
    cudaStreamWaitEvent(main_s, e2, 0);

    dim3 grid(D_OUT / BN, T_TOK / BM);   // (32, 64)
    fused_gemm_kernel<<<grid, 128, SMEM_TOTAL, main_s>>>(base_b, wb, out);
}